// round 16
// baseline (speedup 1.0000x reference)
#include <cuda_runtime.h>
#include <cuda_fp16.h>
#include <math.h>
#include <stdint.h>

// ---------------- problem-size maxima (fixed instance: T=4096,D=1024,F=4096,E=8,k=2)
#define T_MAX    4096
#define E_MAX    8
#define SLOT_MAX 2
#define D_MAX    1024
#define F_MAX    4096
#define RPAD_MAX (T_MAX * SLOT_MAX + E_MAX * 128)   // 9216
#define TILES_MAX (RPAD_MAX / 128)                  // 72

// ---------------- device scratch (static: no allocation anywhere)
__device__ __half g_Xh [(size_t)RPAD_MAX * D_MAX];          // gathered tokens, fp16
__device__ __half g_Hh [(size_t)RPAD_MAX * F_MAX];          // hidden, fp16
__device__ __half g_Oh [(size_t)RPAD_MAX * D_MAX];          // expert outputs, fp16
__device__ __half g_W1h[(size_t)E_MAX * F_MAX * D_MAX];     // w1^T [E][F][D] fp16
__device__ __half g_W2h[(size_t)E_MAX * D_MAX * F_MAX];     // w2^T [E][D][F] fp16
__device__ int    g_sel [T_MAX * SLOT_MAX];
__device__ float  g_wts [T_MAX * SLOT_MAX];
__device__ int    g_pos [T_MAX * SLOT_MAX];
__device__ int    g_count [E_MAX];
__device__ int    g_cursor[E_MAX];
__device__ int    g_off   [E_MAX + 1];
__device__ int    g_tile2e[TILES_MAX];
__device__ int    g_row2tok[RPAD_MAX];

// ---------------- helpers ----------------
__device__ __forceinline__ uint32_t smem_u32(const void* p) {
    uint32_t a;
    asm("{ .reg .u64 t; cvta.to.shared.u64 t, %1; cvt.u32.u64 %0, t; }" : "=r"(a) : "l"(p));
    return a;
}
__device__ __forceinline__ void cp16(uint32_t dst, const void* src) {
    asm volatile("cp.async.cg.shared.global [%0], [%1], 16;" :: "r"(dst), "l"(src));
}
#define CP_COMMIT() asm volatile("cp.async.commit_group;" ::: "memory")
#define CP_WAIT1()  asm volatile("cp.async.wait_group 1;" ::: "memory")

// fp16 tensor op, baseline target (compiles for compute_103): K=16 per instruction
__device__ __forceinline__ void mma16n8k16(float* c,
                                           uint32_t a0, uint32_t a1, uint32_t a2, uint32_t a3,
                                           uint32_t b0, uint32_t b1) {
    asm volatile(
        "mma.sync.aligned.m16n8k16.row.col.f32.f16.f16.f32 "
        "{%0,%1,%2,%3}, {%4,%5,%6,%7}, {%8,%9}, {%0,%1,%2,%3};"
        : "+f"(c[0]), "+f"(c[1]), "+f"(c[2]), "+f"(c[3])
        : "r"(a0), "r"(a1), "r"(a2), "r"(a3), "r"(b0), "r"(b1));
}

// ---------------- init ----------------
__global__ void k_init() {
    int i = blockIdx.x * blockDim.x + threadIdx.x;
    if (i < RPAD_MAX)  g_row2tok[i] = -1;
    if (i < TILES_MAX) g_tile2e[i]  = -1;
    if (i < E_MAX)   { g_count[i] = 0; g_cursor[i] = 0; }
}

// ---------------- router: one block per token, float4-vectorized (R14-proven) ----------------
__global__ void k_router(const float* __restrict__ x, const float* __restrict__ gw,
                         const float* __restrict__ gb, const int* __restrict__ topk_p,
                         int D, int E) {
    int t = blockIdx.x;
    int tid = threadIdx.x, lane = tid & 31, warp = tid >> 5;
    int D4 = D >> 2;

    float acc[E_MAX];
    #pragma unroll
    for (int e = 0; e < E_MAX; e++) acc[e] = 0.f;

    const float4* xr4 = (const float4*)(x + (size_t)t * D);
    for (int d4 = tid; d4 < D4; d4 += blockDim.x) {
        float4 xv = xr4[d4];
        #pragma unroll
        for (int e = 0; e < E_MAX; e++) {
            if (e >= E) break;
            float4 wv = ((const float4*)(gw + (size_t)e * D))[d4];
            acc[e] += xv.x * wv.x + xv.y * wv.y + xv.z * wv.z + xv.w * wv.w;
        }
    }
    __shared__ float sred[E_MAX][8];
    for (int e = 0; e < E; e++) {
        float v = acc[e];
        #pragma unroll
        for (int o = 16; o > 0; o >>= 1) v += __shfl_down_sync(0xffffffffu, v, o);
        if (lane == 0) sred[e][warp] = v;
    }
    __syncthreads();
    if (tid == 0) {
        int nw = blockDim.x >> 5;
        float logit[E_MAX], mx = -1e30f;
        for (int e = 0; e < E; e++) {
            float s = gb[e];
            for (int w = 0; w < nw; w++) s += sred[e][w];
            logit[e] = s; mx = fmaxf(mx, s);
        }
        float p[E_MAX], Z = 0.f;
        for (int e = 0; e < E; e++) { p[e] = expf(logit[e] - mx); Z += p[e]; }
        float invZ = 1.f / Z;
        for (int e = 0; e < E; e++) p[e] *= invZ;

        int k = topk_p ? *topk_p : 2;
        if (k > SLOT_MAX) k = SLOT_MAX;
        if (k < 1) k = 1;
        bool used[E_MAX];
        for (int e = 0; e < E; e++) used[e] = false;
        float wsum = 0.f;
        int sels[SLOT_MAX]; float wv[SLOT_MAX];
        for (int s = 0; s < k; s++) {
            int best = 0; float bv = -1.f;
            for (int e = 0; e < E; e++)
                if (!used[e] && p[e] > bv) { bv = p[e]; best = e; }  // strict > => lowest idx on tie
            used[best] = true;
            sels[s] = best; wv[s] = bv; wsum += bv;
            atomicAdd(&g_count[best], 1);
        }
        float inv = 1.f / wsum;
        for (int s = 0; s < k; s++) { g_sel[t*SLOT_MAX+s] = sels[s]; g_wts[t*SLOT_MAX+s] = wv[s]*inv; }
        for (int s = k; s < SLOT_MAX; s++) { g_sel[t*SLOT_MAX+s] = -1; g_wts[t*SLOT_MAX+s] = 0.f; }
    }
}

// ---------------- scan ----------------
__global__ void k_scan(int E) {
    if (threadIdx.x != 0 || blockIdx.x != 0) return;
    int off = 0;
    for (int e = 0; e < E; e++) {
        g_off[e] = off;
        int tiles = (g_count[e] + 127) >> 7;
        for (int i = 0; i < tiles; i++) g_tile2e[(off >> 7) + i] = e;
        off += tiles << 7;
    }
    g_off[E] = off;
}

// ---------------- assign ----------------
__global__ void k_assign(int T) {
    int idx = blockIdx.x * blockDim.x + threadIdx.x;
    if (idx >= T * SLOT_MAX) return;
    int t = idx / SLOT_MAX, s = idx % SLOT_MAX;
    int e = g_sel[t * SLOT_MAX + s];
    if (e < 0) { g_pos[t * SLOT_MAX + s] = -1; return; }
    int pos = atomicAdd(&g_cursor[e], 1);
    int row = g_off[e] + pos;
    g_row2tok[row] = t;
    g_pos[t * SLOT_MAX + s] = row;
}

// ---------------- gather: fp32 tokens -> fp16 rows (zeros for pad) ----------------
__global__ void k_gather(const float* __restrict__ x, int D) {
    int row = blockIdx.x;
    int tok = g_row2tok[row];
    __half2* dst = (__half2*)(g_Xh + (size_t)row * D);
    if (tok >= 0) {
        const float2* src = (const float2*)(x + (size_t)tok * D);
        for (int c = threadIdx.x; c < (D >> 1); c += blockDim.x) {
            float2 v = src[c];
            dst[c] = __floats2half2_rn(v.x, v.y);
        }
    } else {
        __half2 z = __floats2half2_rn(0.f, 0.f);
        for (int c = threadIdx.x; c < (D >> 1); c += blockDim.x) dst[c] = z;
    }
}

// ---------------- weight convert+transpose: fp32 [E][K][N] -> fp16 [E][N][K] ----------------
__global__ void k_wconv(const float* __restrict__ W, __half* __restrict__ Wt, int K, int N) {
    __shared__ float t[32][33];
    int e = blockIdx.z;
    const float* We = W + (size_t)e * K * N;
    __half* Wte = Wt + (size_t)e * N * K;
    int n0 = blockIdx.x * 32, k0 = blockIdx.y * 32;
    #pragma unroll
    for (int i = 0; i < 32; i += 8) {
        int k = k0 + threadIdx.y + i;
        t[threadIdx.y + i][threadIdx.x] = We[(size_t)k * N + n0 + threadIdx.x];
    }
    __syncthreads();
    #pragma unroll
    for (int i = 0; i < 32; i += 8) {
        int n = n0 + threadIdx.y + i;
        Wte[(size_t)n * K + k0 + threadIdx.x] = __float2half_rn(t[threadIdx.x][threadIdx.y + i]);
    }
}

// ---------------- fp16 tensor GEMM: 128x128 tile, m16n8k16, BK=64, 3-stage cp.async ----------------
// A: [rows][K] halfs k-contig; Wt: [E][Ntot][K] halfs k-contig; bias: [E][Ntot] fp32;
// act=1 -> silu. Output fp16. C row stride Ntot.
#define BK  64                  // halfs per chunk = 128B rows
#define TS2 36                  // smem row stride in b32 (32 data + 4 pad): 36≡4 mod 32 -> conflict-free
#define BUF32 (128 * TS2)       // b32 per buffer (A or B) = 4608 -> 18432 B
#define GSMEM (6 * BUF32 * 4)   // 3 A + 3 B buffers = 110592 B (2 CTA/SM: 221184 <= 228KB)

__global__ void __launch_bounds__(256, 2)
k_gemm_h(const __half* __restrict__ Abase, const __half* __restrict__ Wt,
         const float* __restrict__ Ball, __half* __restrict__ Cout,
         int Ntot, int K, int act) {
    int tile_m = blockIdx.y, tile_n = blockIdx.x;
    int e = g_tile2e[tile_m];
    if (e < 0) return;

    extern __shared__ uint32_t smu[];
    uint32_t* As = smu;                  // [3][128][TS2]
    uint32_t* Bs = smu + 3 * BUF32;      // [3][128][TS2]

    const __half* A = Abase + (size_t)tile_m * 128 * K;
    const __half* B = Wt + (size_t)e * Ntot * K + (size_t)tile_n * 128 * K;  // [n][k]

    int tid = threadIdx.x, lane = tid & 31, wid = tid >> 5;
    int wm = wid & 1, wn = wid >> 1;     // warp tile 64(m) x 32(n)
    int grp = lane >> 2, thr = lane & 3;

    // staging: 1024 16B-segs per tile (128 rows x 8); thread covers row tid>>1, segs (tid&1)*4 + j
    int r0 = tid >> 1;
    int cHalf = (tid & 1) * 32;          // half offset within row (0 or 32)
    uint32_t aS = smem_u32(As), bS = smem_u32(Bs);
    uint32_t offB = (uint32_t)((r0 * TS2 + (tid & 1) * 16) * 4);   // byte offset in buffer
    const __half* aP = A + (size_t)r0 * K + cHalf;
    const __half* bP = B + (size_t)r0 * K + cHalf;

    float acc[4][4][4];
    #pragma unroll
    for (int mf = 0; mf < 4; mf++)
        #pragma unroll
        for (int nf = 0; nf < 4; nf++)
            #pragma unroll
            for (int c = 0; c < 4; c++) acc[mf][nf][c] = 0.f;

    int nk = K / BK;
    auto stage = [&](int kc, int b) {
        uint32_t ad = aS + (uint32_t)(b * BUF32 * 4) + offB;
        uint32_t bd = bS + (uint32_t)(b * BUF32 * 4) + offB;
        const __half* as = aP + kc * BK;
        const __half* bs = bP + kc * BK;
        #pragma unroll
        for (int j = 0; j < 4; j++) {
            cp16(ad + j * 16, as + j * 8);
            cp16(bd + j * 16, bs + j * 8);
        }
    };

    // prologue: prefetch depth 2
    stage(0, 0); CP_COMMIT();
    if (nk > 1) stage(1, 1);
    CP_COMMIT();

    int buf = 0;
    for (int kc = 0; kc < nk; kc++) {
        CP_WAIT1();                      // chunk kc landed (<=1 group in flight)
        __syncthreads();                 // prior chunk's readers done -> safe to restage sb
        int sb = buf + 2; if (sb >= 3) sb -= 3;
        if (kc + 2 < nk) stage(kc + 2, sb);
        CP_COMMIT();

        const uint32_t* Ab = As + buf * BUF32;
        const uint32_t* Bb = Bs + buf * BUF32;
        #pragma unroll
        for (int ks2 = 0; ks2 < 32; ks2 += 8) {    // four K=16 steps (b32 offsets 0,8,16,24)
            uint32_t af[4][4], bf[4][2];
            #pragma unroll
            for (int mf = 0; mf < 4; mf++) {
                int base = (wm * 64 + mf * 16 + grp) * TS2 + ks2 + thr;
                af[mf][0] = Ab[base];
                af[mf][1] = Ab[base + 8 * TS2];
                af[mf][2] = Ab[base + 4];
                af[mf][3] = Ab[base + 8 * TS2 + 4];
            }
            #pragma unroll
            for (int nf = 0; nf < 4; nf++) {
                int base = (wn * 32 + nf * 8 + grp) * TS2 + ks2 + thr;
                bf[nf][0] = Bb[base];
                bf[nf][1] = Bb[base + 4];
            }
            #pragma unroll
            for (int mf = 0; mf < 4; mf++)
                #pragma unroll
                for (int nf = 0; nf < 4; nf++)
                    mma16n8k16(&acc[mf][nf][0], af[mf][0], af[mf][1], af[mf][2], af[mf][3],
                               bf[nf][0], bf[nf][1]);
        }
        buf = buf + 1; if (buf == 3) buf = 0;
    }

    // epilogue: bias (+ SiLU), fp16 stores
    const float* bias = Ball + (size_t)e * Ntot + (size_t)tile_n * 128;
    __half* Cb = Cout + (size_t)tile_m * 128 * Ntot + (size_t)tile_n * 128;
    #pragma unroll
    for (int mf = 0; mf < 4; mf++) {
        #pragma unroll
        for (int nf = 0; nf < 4; nf++) {
            int row = wm * 64 + mf * 16 + grp;
            int col = wn * 32 + nf * 8 + thr * 2;
            float b0 = bias[col], b1 = bias[col + 1];
            float v00 = acc[mf][nf][0] + b0, v01 = acc[mf][nf][1] + b1;
            float v10 = acc[mf][nf][2] + b0, v11 = acc[mf][nf][3] + b1;
            if (act) {
                v00 = v00 / (1.f + __expf(-v00));
                v01 = v01 / (1.f + __expf(-v01));
                v10 = v10 / (1.f + __expf(-v10));
                v11 = v11 / (1.f + __expf(-v11));
            }
            *(__half2*)(Cb + (size_t)row * Ntot + col)       = __floats2half2_rn(v00, v01);
            *(__half2*)(Cb + (size_t)(row + 8) * Ntot + col) = __floats2half2_rn(v10, v11);
        }
    }
}

// ---------------- combine: out[t] = sum_s w_s * O_h[row_s]  (fp16 in, fp32 out) ----------------
__global__ void k_combine(float* __restrict__ out, int D) {
    int t = blockIdx.x;
    int rows[SLOT_MAX]; float ws[SLOT_MAX];
    #pragma unroll
    for (int s = 0; s < SLOT_MAX; s++) { rows[s] = g_pos[t*SLOT_MAX+s]; ws[s] = g_wts[t*SLOT_MAX+s]; }
    float4* dst = (float4*)(out + (size_t)t * D);
    for (int c = threadIdx.x; c < (D >> 2); c += blockDim.x) {
        float4 a = make_float4(0.f, 0.f, 0.f, 0.f);
        #pragma unroll
        for (int s = 0; s < SLOT_MAX; s++) {
            if (rows[s] < 0) continue;
            const __half2* hp = (const __half2*)(g_Oh + (size_t)rows[s] * D) + c * 2;
            float2 v0 = __half22float2(hp[0]);
            float2 v1 = __half22float2(hp[1]);
            a.x = fmaf(ws[s], v0.x, a.x); a.y = fmaf(ws[s], v0.y, a.y);
            a.z = fmaf(ws[s], v1.x, a.z); a.w = fmaf(ws[s], v1.y, a.w);
        }
        dst[c] = a;
    }
}

// ---------------- launch ----------------
extern "C" void kernel_launch(void* const* d_in, const int* in_sizes, int n_in,
                              void* d_out, int out_size) {
    const float* x    = (const float*)d_in[0];
    const float* gw   = (const float*)d_in[1];
    const float* gb   = (const float*)d_in[2];
    const float* w1   = (const float*)d_in[3];
    const float* b1   = (const float*)d_in[4];
    const float* w2   = (const float*)d_in[5];
    const float* b2   = (const float*)d_in[6];
    const int*   topk = (n_in > 7) ? (const int*)d_in[7] : nullptr;
    float* out = (float*)d_out;

    const int E = in_sizes[2];
    const int D = in_sizes[1] / E;
    const int F = in_sizes[4] / E;
    const int T = in_sizes[0] / D;

    __half *Xh = nullptr, *Hh = nullptr, *Oh = nullptr, *W1h = nullptr, *W2h = nullptr;
    cudaGetSymbolAddress((void**)&Xh,  g_Xh);
    cudaGetSymbolAddress((void**)&Hh,  g_Hh);
    cudaGetSymbolAddress((void**)&Oh,  g_Oh);
    cudaGetSymbolAddress((void**)&W1h, g_W1h);
    cudaGetSymbolAddress((void**)&W2h, g_W2h);

    cudaFuncSetAttribute(k_gemm_h, cudaFuncAttributeMaxDynamicSharedMemorySize, GSMEM);

    // side stream + events: created once on the first (uncaptured) correctness call;
    // during capture only EventRecord/StreamWaitEvent/launches are issued (all capturable).
    static cudaStream_t s_side = nullptr;
    static cudaEvent_t  s_fork = nullptr, s_w1 = nullptr, s_w2 = nullptr;
    if (!s_side) {
        cudaStreamCreateWithFlags(&s_side, cudaStreamNonBlocking);
        cudaEventCreateWithFlags(&s_fork, cudaEventDisableTiming);
        cudaEventCreateWithFlags(&s_w1,   cudaEventDisableTiming);
        cudaEventCreateWithFlags(&s_w2,   cudaEventDisableTiming);
    }

    dim3 bt(32, 8);

    // fork: weight conversion runs on the side stream
    cudaEventRecord(s_fork, 0);
    cudaStreamWaitEvent(s_side, s_fork, 0);
    k_wconv<<<dim3(F / 32, D / 32, E), bt, 0, s_side>>>(w1, W1h, D, F);  // [E][D][F]->[E][F][D]
    cudaEventRecord(s_w1, s_side);
    k_wconv<<<dim3(D / 32, F / 32, E), bt, 0, s_side>>>(w2, W2h, F, D);  // [E][F][D]->[E][D][F]
    cudaEventRecord(s_w2, s_side);

    // main stream: routing pipeline (independent of weights)
    k_init<<<(RPAD_MAX + 255) / 256, 256>>>();
    k_router<<<T, 256>>>(x, gw, gb, topk, D, E);
    k_scan<<<1, 32>>>(E);
    k_assign<<<(T * SLOT_MAX + 255) / 256, 256>>>(T);
    k_gather<<<RPAD_MAX, 256>>>(x, D);

    // join 1: GEMM1 needs W1h (wconv2 keeps running under GEMM1)
    cudaStreamWaitEvent(0, s_w1, 0);
    k_gemm_h<<<dim3(F / 128, TILES_MAX), 256, GSMEM>>>(Xh, W1h, b1, Hh, F, D, 1);

    // join 2: GEMM2 needs W2h
    cudaStreamWaitEvent(0, s_w2, 0);
    k_gemm_h<<<dim3(D / 128, TILES_MAX), 256, GSMEM>>>(Hh, W2h, b2, Oh, D, F, 0);

    k_combine<<<T, 256>>>(out, D);
}

// round 17
// speedup vs baseline: 1.2411x; 1.2411x over previous
#include <cuda_runtime.h>
#include <cuda_fp16.h>
#include <math.h>
#include <stdint.h>

// ---------------- problem-size maxima (fixed instance: T=4096,D=1024,F=4096,E=8,k=2)
#define T_MAX    4096
#define E_MAX    8
#define SLOT_MAX 2
#define D_MAX    1024
#define F_MAX    4096
#define RPAD_MAX (T_MAX * SLOT_MAX + E_MAX * 128)   // 9216
#define TILES_MAX (RPAD_MAX / 128)                  // 72

// ---------------- device scratch (static: no allocation anywhere)
__device__ __half g_Xh [(size_t)RPAD_MAX * D_MAX];          // gathered tokens, fp16
__device__ __half g_Hh [(size_t)RPAD_MAX * F_MAX];          // hidden, fp16
__device__ float  g_O  [(size_t)RPAD_MAX * D_MAX];          // expert outputs, fp32
__device__ __half g_W1h[(size_t)E_MAX * F_MAX * D_MAX];     // w1^T [E][F][D] fp16
__device__ __half g_W2h[(size_t)E_MAX * D_MAX * F_MAX];     // w2^T [E][D][F] fp16
__device__ int    g_sel [T_MAX * SLOT_MAX];
__device__ float  g_wts [T_MAX * SLOT_MAX];
__device__ int    g_pos [T_MAX * SLOT_MAX];
__device__ int    g_count [E_MAX];
__device__ int    g_cursor[E_MAX];
__device__ int    g_off   [E_MAX + 1];
__device__ int    g_tile2e[TILES_MAX];
__device__ int    g_row2tok[RPAD_MAX];

// ---------------- helpers ----------------
__device__ __forceinline__ uint32_t smem_u32(const void* p) {
    uint32_t a;
    asm("{ .reg .u64 t; cvta.to.shared.u64 t, %1; cvt.u32.u64 %0, t; }" : "=r"(a) : "l"(p));
    return a;
}
__device__ __forceinline__ void cp16(uint32_t dst, const void* src) {
    asm volatile("cp.async.cg.shared.global [%0], [%1], 16;" :: "r"(dst), "l"(src));
}
#define CP_COMMIT() asm volatile("cp.async.commit_group;" ::: "memory")
#define CP_WAIT0()  asm volatile("cp.async.wait_group 0;" ::: "memory")

// fp16 tensor op, baseline target (compiles for compute_103): K=16 per instruction
__device__ __forceinline__ void mma16n8k16(float* c,
                                           uint32_t a0, uint32_t a1, uint32_t a2, uint32_t a3,
                                           uint32_t b0, uint32_t b1) {
    asm volatile(
        "mma.sync.aligned.m16n8k16.row.col.f32.f16.f16.f32 "
        "{%0,%1,%2,%3}, {%4,%5,%6,%7}, {%8,%9}, {%0,%1,%2,%3};"
        : "+f"(c[0]), "+f"(c[1]), "+f"(c[2]), "+f"(c[3])
        : "r"(a0), "r"(a1), "r"(a2), "r"(a3), "r"(b0), "r"(b1));
}

// ---------------- init ----------------
__global__ void k_init() {
    int i = blockIdx.x * blockDim.x + threadIdx.x;
    if (i < RPAD_MAX)  g_row2tok[i] = -1;
    if (i < TILES_MAX) g_tile2e[i]  = -1;
    if (i < E_MAX)   { g_count[i] = 0; g_cursor[i] = 0; }
}

// ---------------- router: one block per token, float4-vectorized (R14-proven) ----------------
__global__ void k_router(const float* __restrict__ x, const float* __restrict__ gw,
                         const float* __restrict__ gb, const int* __restrict__ topk_p,
                         int D, int E) {
    int t = blockIdx.x;
    int tid = threadIdx.x, lane = tid & 31, warp = tid >> 5;
    int D4 = D >> 2;

    float acc[E_MAX];
    #pragma unroll
    for (int e = 0; e < E_MAX; e++) acc[e] = 0.f;

    const float4* xr4 = (const float4*)(x + (size_t)t * D);
    for (int d4 = tid; d4 < D4; d4 += blockDim.x) {
        float4 xv = xr4[d4];
        #pragma unroll
        for (int e = 0; e < E_MAX; e++) {
            if (e >= E) break;
            float4 wv = ((const float4*)(gw + (size_t)e * D))[d4];
            acc[e] += xv.x * wv.x + xv.y * wv.y + xv.z * wv.z + xv.w * wv.w;
        }
    }
    __shared__ float sred[E_MAX][8];
    for (int e = 0; e < E; e++) {
        float v = acc[e];
        #pragma unroll
        for (int o = 16; o > 0; o >>= 1) v += __shfl_down_sync(0xffffffffu, v, o);
        if (lane == 0) sred[e][warp] = v;
    }
    __syncthreads();
    if (tid == 0) {
        int nw = blockDim.x >> 5;
        float logit[E_MAX], mx = -1e30f;
        for (int e = 0; e < E; e++) {
            float s = gb[e];
            for (int w = 0; w < nw; w++) s += sred[e][w];
            logit[e] = s; mx = fmaxf(mx, s);
        }
        float p[E_MAX], Z = 0.f;
        for (int e = 0; e < E; e++) { p[e] = expf(logit[e] - mx); Z += p[e]; }
        float invZ = 1.f / Z;
        for (int e = 0; e < E; e++) p[e] *= invZ;

        int k = topk_p ? *topk_p : 2;
        if (k > SLOT_MAX) k = SLOT_MAX;
        if (k < 1) k = 1;
        bool used[E_MAX];
        for (int e = 0; e < E; e++) used[e] = false;
        float wsum = 0.f;
        int sels[SLOT_MAX]; float wv[SLOT_MAX];
        for (int s = 0; s < k; s++) {
            int best = 0; float bv = -1.f;
            for (int e = 0; e < E; e++)
                if (!used[e] && p[e] > bv) { bv = p[e]; best = e; }  // strict > => lowest idx on tie
            used[best] = true;
            sels[s] = best; wv[s] = bv; wsum += bv;
            atomicAdd(&g_count[best], 1);
        }
        float inv = 1.f / wsum;
        for (int s = 0; s < k; s++) { g_sel[t*SLOT_MAX+s] = sels[s]; g_wts[t*SLOT_MAX+s] = wv[s]*inv; }
        for (int s = k; s < SLOT_MAX; s++) { g_sel[t*SLOT_MAX+s] = -1; g_wts[t*SLOT_MAX+s] = 0.f; }
    }
}

// ---------------- scan ----------------
__global__ void k_scan(int E) {
    if (threadIdx.x != 0 || blockIdx.x != 0) return;
    int off = 0;
    for (int e = 0; e < E; e++) {
        g_off[e] = off;
        int tiles = (g_count[e] + 127) >> 7;
        for (int i = 0; i < tiles; i++) g_tile2e[(off >> 7) + i] = e;
        off += tiles << 7;
    }
    g_off[E] = off;
}

// ---------------- assign ----------------
__global__ void k_assign(int T) {
    int idx = blockIdx.x * blockDim.x + threadIdx.x;
    if (idx >= T * SLOT_MAX) return;
    int t = idx / SLOT_MAX, s = idx % SLOT_MAX;
    int e = g_sel[t * SLOT_MAX + s];
    if (e < 0) { g_pos[t * SLOT_MAX + s] = -1; return; }
    int pos = atomicAdd(&g_cursor[e], 1);
    int row = g_off[e] + pos;
    g_row2tok[row] = t;
    g_pos[t * SLOT_MAX + s] = row;
}

// ---------------- gather: fp32 tokens -> fp16 rows (zeros for pad) ----------------
__global__ void k_gather(const float* __restrict__ x, int D) {
    int row = blockIdx.x;
    int tok = g_row2tok[row];
    __half2* dst = (__half2*)(g_Xh + (size_t)row * D);
    if (tok >= 0) {
        const float2* src = (const float2*)(x + (size_t)tok * D);
        for (int c = threadIdx.x; c < (D >> 1); c += blockDim.x) {
            float2 v = src[c];
            dst[c] = __floats2half2_rn(v.x, v.y);
        }
    } else {
        __half2 z = __floats2half2_rn(0.f, 0.f);
        for (int c = threadIdx.x; c < (D >> 1); c += blockDim.x) dst[c] = z;
    }
}

// ---------------- weight convert+transpose: fp32 [E][K][N] -> fp16 [E][N][K] ----------------
__global__ void k_wconv(const float* __restrict__ W, __half* __restrict__ Wt, int K, int N) {
    __shared__ float t[32][33];
    int e = blockIdx.z;
    const float* We = W + (size_t)e * K * N;
    __half* Wte = Wt + (size_t)e * N * K;
    int n0 = blockIdx.x * 32, k0 = blockIdx.y * 32;
    #pragma unroll
    for (int i = 0; i < 32; i += 8) {
        int k = k0 + threadIdx.y + i;
        t[threadIdx.y + i][threadIdx.x] = We[(size_t)k * N + n0 + threadIdx.x];
    }
    __syncthreads();
    #pragma unroll
    for (int i = 0; i < 32; i += 8) {
        int n = n0 + threadIdx.y + i;
        Wte[(size_t)n * K + k0 + threadIdx.x] = __float2half_rn(t[threadIdx.x][threadIdx.y + i]);
    }
}

// ---------------- fp16 tensor GEMM: 128x128 tile, m16n8k16, paired-chunk pipeline ----------------
// 4 buffers of BK=32 halfs; TWO chunks computed per wait/sync -> half the barrier events,
// SMEM unchanged (2 CTA/SM). A: [rows][K]; Wt: [E][Ntot][K]; bias fp32.
// act=1 -> silu, store fp16 (H);  act=0 -> store fp32 (O). C row stride Ntot.
#define BK  32                  // halfs per chunk = 64B rows
#define TS2 20                  // smem row stride in b32 (16 data + 4 pad): lanes g*20+t -> 32 banks
#define BUF32 (128 * TS2)       // b32 per buffer (A or B) = 2560 -> 10240 B
#define GSMEM (8 * BUF32 * 4)   // 4 A + 4 B buffers = 81920 B

__global__ void __launch_bounds__(256, 2)
k_gemm_h(const __half* __restrict__ Abase, const __half* __restrict__ Wt,
         const float* __restrict__ Ball, void* __restrict__ Cout,
         int Ntot, int K, int act) {
    int tile_m = blockIdx.y, tile_n = blockIdx.x;
    int e = g_tile2e[tile_m];
    if (e < 0) return;

    extern __shared__ uint32_t smu[];
    uint32_t* As = smu;                  // [4][128][TS2]
    uint32_t* Bs = smu + 4 * BUF32;      // [4][128][TS2]

    const __half* A = Abase + (size_t)tile_m * 128 * K;
    const __half* B = Wt + (size_t)e * Ntot * K + (size_t)tile_n * 128 * K;  // [n][k]

    int tid = threadIdx.x, lane = tid & 31, wid = tid >> 5;
    int wm = wid & 1, wn = wid >> 1;     // warp tile 64(m) x 32(n)
    int grp = lane >> 2, thr = lane & 3;

    // staging: 512 16B-segs per tile (128 rows x 4); thread covers rows r0 and r0+64
    int r0 = tid >> 2, c16 = tid & 3;
    uint32_t aS = smem_u32(As), bS = smem_u32(Bs);
    uint32_t off0 = (uint32_t)((r0 * TS2 + c16 * 4) * 4);
    uint32_t off1 = off0 + (uint32_t)(64 * TS2 * 4);
    const __half* aP0 = A + (size_t)r0 * K + c16 * 8;
    const __half* aP1 = aP0 + (size_t)64 * K;
    const __half* bP0 = B + (size_t)r0 * K + c16 * 8;
    const __half* bP1 = bP0 + (size_t)64 * K;

    float acc[4][4][4];
    #pragma unroll
    for (int mf = 0; mf < 4; mf++)
        #pragma unroll
        for (int nf = 0; nf < 4; nf++)
            #pragma unroll
            for (int c = 0; c < 4; c++) acc[mf][nf][c] = 0.f;

    int nk = K / BK;                     // even (32 or 128)
    auto stage = [&](int kc) {           // chunk kc -> buffer kc&3
        int b = kc & 3;
        uint32_t ad = aS + (uint32_t)(b * BUF32 * 4);
        uint32_t bd = bS + (uint32_t)(b * BUF32 * 4);
        int kh = kc * BK;
        cp16(ad + off0, aP0 + kh);
        cp16(ad + off1, aP1 + kh);
        cp16(bd + off0, bP0 + kh);
        cp16(bd + off1, bP1 + kh);
    };
    auto compute = [&](int kc) {         // consume buffer kc&3
        const uint32_t* Ab = As + (kc & 3) * BUF32;
        const uint32_t* Bb = Bs + (kc & 3) * BUF32;
        #pragma unroll
        for (int ks2 = 0; ks2 < 16; ks2 += 8) {   // two K=16 steps (b32 offsets 0, 8)
            uint32_t af[4][4], bf[4][2];
            #pragma unroll
            for (int mf = 0; mf < 4; mf++) {
                int base = (wm * 64 + mf * 16 + grp) * TS2 + ks2 + thr;
                af[mf][0] = Ab[base];
                af[mf][1] = Ab[base + 8 * TS2];
                af[mf][2] = Ab[base + 4];
                af[mf][3] = Ab[base + 8 * TS2 + 4];
            }
            #pragma unroll
            for (int nf = 0; nf < 4; nf++) {
                int base = (wn * 32 + nf * 8 + grp) * TS2 + ks2 + thr;
                bf[nf][0] = Bb[base];
                bf[nf][1] = Bb[base + 4];
            }
            #pragma unroll
            for (int mf = 0; mf < 4; mf++)
                #pragma unroll
                for (int nf = 0; nf < 4; nf++)
                    mma16n8k16(&acc[mf][nf][0], af[mf][0], af[mf][1], af[mf][2], af[mf][3],
                               bf[nf][0], bf[nf][1]);
        }
    };

    // prologue: stage pair 0 (chunks 0,1 -> bufs 0,1)
    stage(0); stage(1); CP_COMMIT();

    for (int kc = 0; kc < nk; kc += 2) {
        CP_WAIT0();                      // pair (kc,kc+1) landed
        __syncthreads();                 // readers of previous pair done -> other half free
        if (kc + 2 < nk) { stage(kc + 2); stage(kc + 3); }
        CP_COMMIT();                     // loads of next pair overlap compute below
        compute(kc);
        compute(kc + 1);
    }

    // epilogue: bias (+ SiLU); act=1 -> fp16 store (H), act=0 -> fp32 store (O)
    const float* bias = Ball + (size_t)e * Ntot + (size_t)tile_n * 128;
    #pragma unroll
    for (int mf = 0; mf < 4; mf++) {
        #pragma unroll
        for (int nf = 0; nf < 4; nf++) {
            int row = wm * 64 + mf * 16 + grp;
            int col = wn * 32 + nf * 8 + thr * 2;
            float b0 = bias[col], b1 = bias[col + 1];
            float v00 = acc[mf][nf][0] + b0, v01 = acc[mf][nf][1] + b1;
            float v10 = acc[mf][nf][2] + b0, v11 = acc[mf][nf][3] + b1;
            if (act) {
                v00 = v00 / (1.f + __expf(-v00));
                v01 = v01 / (1.f + __expf(-v01));
                v10 = v10 / (1.f + __expf(-v10));
                v11 = v11 / (1.f + __expf(-v11));
                __half* Cb = (__half*)Cout + (size_t)tile_m * 128 * Ntot + (size_t)tile_n * 128;
                *(__half2*)(Cb + (size_t)row * Ntot + col)       = __floats2half2_rn(v00, v01);
                *(__half2*)(Cb + (size_t)(row + 8) * Ntot + col) = __floats2half2_rn(v10, v11);
            } else {
                float* Cb = (float*)Cout + (size_t)tile_m * 128 * Ntot + (size_t)tile_n * 128;
                *(float2*)(Cb + (size_t)row * Ntot + col)       = make_float2(v00, v01);
                *(float2*)(Cb + (size_t)(row + 8) * Ntot + col) = make_float2(v10, v11);
            }
        }
    }
}

// ---------------- combine ----------------
__global__ void k_combine(float* __restrict__ out, int D) {
    int t = blockIdx.x;
    int rows[SLOT_MAX]; float ws[SLOT_MAX];
    #pragma unroll
    for (int s = 0; s < SLOT_MAX; s++) { rows[s] = g_pos[t*SLOT_MAX+s]; ws[s] = g_wts[t*SLOT_MAX+s]; }
    float4* dst = (float4*)(out + (size_t)t * D);
    for (int c = threadIdx.x; c < (D >> 2); c += blockDim.x) {
        float4 a = make_float4(0.f, 0.f, 0.f, 0.f);
        #pragma unroll
        for (int s = 0; s < SLOT_MAX; s++) {
            if (rows[s] < 0) continue;
            const float4 v = ((const float4*)(g_O + (size_t)rows[s] * D))[c];
            a.x = fmaf(ws[s], v.x, a.x); a.y = fmaf(ws[s], v.y, a.y);
            a.z = fmaf(ws[s], v.z, a.z); a.w = fmaf(ws[s], v.w, a.w);
        }
        dst[c] = a;
    }
}

// ---------------- launch ----------------
extern "C" void kernel_launch(void* const* d_in, const int* in_sizes, int n_in,
                              void* d_out, int out_size) {
    const float* x    = (const float*)d_in[0];
    const float* gw   = (const float*)d_in[1];
    const float* gb   = (const float*)d_in[2];
    const float* w1   = (const float*)d_in[3];
    const float* b1   = (const float*)d_in[4];
    const float* w2   = (const float*)d_in[5];
    const float* b2   = (const float*)d_in[6];
    const int*   topk = (n_in > 7) ? (const int*)d_in[7] : nullptr;
    float* out = (float*)d_out;

    const int E = in_sizes[2];
    const int D = in_sizes[1] / E;
    const int F = in_sizes[4] / E;
    const int T = in_sizes[0] / D;

    __half *Xh = nullptr, *Hh = nullptr, *W1h = nullptr, *W2h = nullptr;
    float  *O  = nullptr;
    cudaGetSymbolAddress((void**)&Xh,  g_Xh);
    cudaGetSymbolAddress((void**)&Hh,  g_Hh);
    cudaGetSymbolAddress((void**)&O,   g_O);
    cudaGetSymbolAddress((void**)&W1h, g_W1h);
    cudaGetSymbolAddress((void**)&W2h, g_W2h);

    cudaFuncSetAttribute(k_gemm_h, cudaFuncAttributeMaxDynamicSharedMemorySize, GSMEM);

    // side stream + events: created once on the first (uncaptured) correctness call;
    // during capture only EventRecord/StreamWaitEvent/launches are issued (all capturable).
    static cudaStream_t s_side = nullptr;
    static cudaEvent_t  s_fork = nullptr, s_w1 = nullptr, s_w2 = nullptr;
    if (!s_side) {
        cudaStreamCreateWithFlags(&s_side, cudaStreamNonBlocking);
        cudaEventCreateWithFlags(&s_fork, cudaEventDisableTiming);
        cudaEventCreateWithFlags(&s_w1,   cudaEventDisableTiming);
        cudaEventCreateWithFlags(&s_w2,   cudaEventDisableTiming);
    }

    dim3 bt(32, 8);

    // fork: weight conversion runs on the side stream
    cudaEventRecord(s_fork, 0);
    cudaStreamWaitEvent(s_side, s_fork, 0);
    k_wconv<<<dim3(F / 32, D / 32, E), bt, 0, s_side>>>(w1, W1h, D, F);  // [E][D][F]->[E][F][D]
    cudaEventRecord(s_w1, s_side);
    k_wconv<<<dim3(D / 32, F / 32, E), bt, 0, s_side>>>(w2, W2h, F, D);  // [E][F][D]->[E][D][F]
    cudaEventRecord(s_w2, s_side);

    // main stream: routing pipeline (independent of weights)
    k_init<<<(RPAD_MAX + 255) / 256, 256>>>();
    k_router<<<T, 256>>>(x, gw, gb, topk, D, E);
    k_scan<<<1, 32>>>(E);
    k_assign<<<(T * SLOT_MAX + 255) / 256, 256>>>(T);
    k_gather<<<RPAD_MAX, 256>>>(x, D);

    // join 1: GEMM1 needs W1h (wconv2 keeps running under GEMM1)
    cudaStreamWaitEvent(0, s_w1, 0);
    k_gemm_h<<<dim3(F / 128, TILES_MAX), 256, GSMEM>>>(Xh, W1h, b1, Hh, F, D, 1);

    // join 2: GEMM2 needs W2h
    cudaStreamWaitEvent(0, s_w2, 0);
    k_gemm_h<<<dim3(D / 128, TILES_MAX), 256, GSMEM>>>(Hh, W2h, b2, O, D, F, 0);

    k_combine<<<T, 256>>>(out, D);
}